// round 8
// baseline (speedup 1.0000x reference)
#include <cuda_runtime.h>
#include <math.h>

#define BATCH   2
#define SEQ     8192
#define DMODEL  512
#define NHEADS  8
#define HDIM    64
#define WIN     128
#define DHID    2048
#define ROWS    (BATCH*SEQ)      // 16384
#define BHS     (BATCH*NHEADS)   // 16
#define BANDW   (2*WIN+1)        // 257

// ---------------- scratch (static device globals; no allocation) ----------------
__device__ float g_q[BHS*SEQ*HDIM];
__device__ float g_k[BHS*SEQ*HDIM];
__device__ float g_v[BHS*SEQ*HDIM];
__device__ float g_attn[ROWS*DMODEL];
__device__ float g_h[ROWS*DMODEL];
__device__ float g_ff1[(size_t)ROWS*DHID];
__device__ float g_ff2[ROWS*DMODEL];

// ---------------- generic fp32 SGEMM: C = A(MxK) @ B(KxN) (+bias, epilogue) ------
// 128x128 tile, K-tile=16, double-buffered smem, one barrier per K-tile.
// mode 0: ((acc+bias)*scale) scattered to head-major [(b*H+h), s, d]
// mode 1: relu(acc+bias) row-major
// mode 2: acc+bias row-major
__global__ __launch_bounds__(256) void sgemm_kernel(
    const float* __restrict__ A, const float* __restrict__ B,
    const float* __restrict__ bias, float* __restrict__ C,
    int M, int N, int K, int mode, float scale)
{
    __shared__ float As[2][16][128];
    __shared__ float Bs[2][16][128];
    const int tid = threadIdx.x;
    const int bx = blockIdx.x, by = blockIdx.y;
    const int tx = tid & 15, ty = tid >> 4;
    const int arow = tid >> 1, acol = (tid & 1) << 3;   // A: 128 rows x 16 cols
    const int brow = tid >> 5, bcol = (tid & 31) << 2;  // B: rows {brow, brow+8}

    const float* Ap = A + (size_t)(by*128 + arow)*K + acol;
    const float* Bp = B + (size_t)brow*N + bx*128 + bcol;

    float acc[8][8];
#pragma unroll
    for (int i = 0; i < 8; i++)
#pragma unroll
        for (int j = 0; j < 8; j++) acc[i][j] = 0.f;

    // prologue: load K-tile 0 and publish it
    float4 a0 = *reinterpret_cast<const float4*>(Ap);
    float4 a1 = *reinterpret_cast<const float4*>(Ap + 4);
    float4 b0 = *reinterpret_cast<const float4*>(Bp);
    float4 b1 = *reinterpret_cast<const float4*>(Bp + (size_t)8*N);
    int cur = 0;
    As[0][acol+0][arow] = a0.x; As[0][acol+1][arow] = a0.y;
    As[0][acol+2][arow] = a0.z; As[0][acol+3][arow] = a0.w;
    As[0][acol+4][arow] = a1.x; As[0][acol+5][arow] = a1.y;
    As[0][acol+6][arow] = a1.z; As[0][acol+7][arow] = a1.w;
    *reinterpret_cast<float4*>(&Bs[0][brow  ][bcol]) = b0;
    *reinterpret_cast<float4*>(&Bs[0][brow+8][bcol]) = b1;
    __syncthreads();

    for (int k0 = 0; k0 < K; k0 += 16) {
        const bool has_next = (k0 + 16) < K;
        if (has_next) {
            a0 = *reinterpret_cast<const float4*>(Ap + k0 + 16);
            a1 = *reinterpret_cast<const float4*>(Ap + k0 + 20);
            b0 = *reinterpret_cast<const float4*>(Bp + (size_t)(k0 + 16)*N);
            b1 = *reinterpret_cast<const float4*>(Bp + (size_t)(k0 + 24)*N);
        }
#pragma unroll
        for (int kk = 0; kk < 16; kk++) {
            float af[8], bf[8];
            *reinterpret_cast<float4*>(&af[0]) = *reinterpret_cast<const float4*>(&As[cur][kk][ty*8]);
            *reinterpret_cast<float4*>(&af[4]) = *reinterpret_cast<const float4*>(&As[cur][kk][ty*8+4]);
            *reinterpret_cast<float4*>(&bf[0]) = *reinterpret_cast<const float4*>(&Bs[cur][kk][tx*8]);
            *reinterpret_cast<float4*>(&bf[4]) = *reinterpret_cast<const float4*>(&Bs[cur][kk][tx*8+4]);
#pragma unroll
            for (int i = 0; i < 8; i++)
#pragma unroll
                for (int j = 0; j < 8; j++)
                    acc[i][j] += af[i]*bf[j];
        }
        if (has_next) {
            const int nxt = cur ^ 1;
            As[nxt][acol+0][arow] = a0.x; As[nxt][acol+1][arow] = a0.y;
            As[nxt][acol+2][arow] = a0.z; As[nxt][acol+3][arow] = a0.w;
            As[nxt][acol+4][arow] = a1.x; As[nxt][acol+5][arow] = a1.y;
            As[nxt][acol+6][arow] = a1.z; As[nxt][acol+7][arow] = a1.w;
            *reinterpret_cast<float4*>(&Bs[nxt][brow  ][bcol]) = b0;
            *reinterpret_cast<float4*>(&Bs[nxt][brow+8][bcol]) = b1;
            __syncthreads();
            cur = nxt;
        }
    }

    const int crow = by*128 + ty*8;
    const int ccol = bx*128 + tx*8;
    if (mode == 0) {
#pragma unroll
        for (int i = 0; i < 8; i++) {
            int m = crow + i;
            int b = m >> 13, s = m & (SEQ-1);
#pragma unroll
            for (int j = 0; j < 8; j++) {
                int n = ccol + j;
                float v = (acc[i][j] + bias[n]) * scale;
                int hh = n >> 6, dd = n & 63;
                C[(((size_t)(b*NHEADS + hh))*SEQ + s)*HDIM + dd] = v;
            }
        }
    } else if (mode == 1) {
#pragma unroll
        for (int i = 0; i < 8; i++) {
            int m = crow + i;
#pragma unroll
            for (int j = 0; j < 8; j++) {
                int n = ccol + j;
                float v = acc[i][j] + bias[n];
                C[(size_t)m*N + n] = fmaxf(v, 0.f);
            }
        }
    } else {
#pragma unroll
        for (int i = 0; i < 8; i++) {
            int m = crow + i;
#pragma unroll
            for (int j = 0; j < 8; j++) {
                int n = ccol + j;
                C[(size_t)m*N + n] = acc[i][j] + bias[n];
            }
        }
    }
}

// ---------------- sliding-window attention -------------------------------------
// Block: 32 queries of one (b,h); keys window [qbase-128, qbase+160) = 288 keys.
// smem: kT[64][288], v[288][64], qT[64][32], probs[32][288]  -> 192,512 B dynamic.
#define QB 32
#define KB 288

__global__ __launch_bounds__(256) void attn_kernel(float* __restrict__ score_out)
{
    extern __shared__ float sm[];
    float* kT  = sm;                       // [64][288]
    float* vv  = kT + 64*KB;               // [288][64]
    float* qT  = vv + KB*64;               // [64][32]
    float* ps  = qT + 64*QB;               // [32][288]

    const int bh = blockIdx.y;
    const int qbase = blockIdx.x * QB;
    const int kbase = qbase - WIN;
    const int tid = threadIdx.x;

    const float* Qg = g_q + (size_t)bh*SEQ*HDIM;
    const float* Kg = g_k + (size_t)bh*SEQ*HDIM;
    const float* Vg = g_v + (size_t)bh*SEQ*HDIM;

    // load K (transposed), V, Q (transposed)
    for (int idx = tid; idx < KB*HDIM; idx += 256) {
        int j = idx >> 6, d = idx & 63;
        int gj = kbase + j;
        float kvv = 0.f, vvv = 0.f;
        if (gj >= 0 && gj < SEQ) {
            kvv = Kg[(size_t)gj*HDIM + d];
            vvv = Vg[(size_t)gj*HDIM + d];
        }
        kT[d*KB + j] = kvv;
        vv[idx]      = vvv;
    }
    for (int idx = tid; idx < QB*HDIM; idx += 256) {
        int qi = idx >> 6, d = idx & 63;
        qT[d*QB + qi] = Qg[(size_t)(qbase + qi)*HDIM + d];
    }
    __syncthreads();

    const int ty = tid >> 5;       // warp 0..7 -> queries 4ty..4ty+3
    const int lane = tid & 31;     // keys lane + 32*kk

    // phase 1: scores
    float s[4][9];
#pragma unroll
    for (int i = 0; i < 4; i++)
#pragma unroll
        for (int kk = 0; kk < 9; kk++) s[i][kk] = 0.f;

    for (int d = 0; d < HDIM; d++) {
        float qv[4], kv[9];
#pragma unroll
        for (int i = 0; i < 4; i++) qv[i] = qT[d*QB + ty*4 + i];
#pragma unroll
        for (int kk = 0; kk < 9; kk++) kv[kk] = kT[d*KB + kk*32 + lane];
#pragma unroll
        for (int i = 0; i < 4; i++)
#pragma unroll
            for (int kk = 0; kk < 9; kk++)
                s[i][kk] += qv[i]*kv[kk];
    }

    // mask + softmax per query (cross-lane over the warp)
#pragma unroll
    for (int qi = 0; qi < 4; qi++) {
        const int ql = ty*4 + qi;
        float sv[9];
        float m = -3.0e38f;
#pragma unroll
        for (int kk = 0; kk < 9; kk++) {
            int j = kk*32 + lane;
            int gj = kbase + j;
            int t = j - ql;
            bool ok = (t >= 0) && (t <= 2*WIN) && (gj >= 0) && (gj < SEQ);
            sv[kk] = ok ? s[qi][kk] : -1.0e9f;
            m = fmaxf(m, sv[kk]);
        }
#pragma unroll
        for (int off = 16; off > 0; off >>= 1)
            m = fmaxf(m, __shfl_xor_sync(0xffffffffu, m, off));
        float e[9], sum = 0.f;
#pragma unroll
        for (int kk = 0; kk < 9; kk++) { e[kk] = expf(sv[kk] - m); sum += e[kk]; }
#pragma unroll
        for (int off = 16; off > 0; off >>= 1)
            sum += __shfl_xor_sync(0xffffffffu, sum, off);
        float inv = 1.f / sum;
#pragma unroll
        for (int kk = 0; kk < 9; kk++)
            ps[ql*KB + kk*32 + lane] = e[kk]*inv;
    }
    __syncthreads();

    // band output: score[(bh, i, t)] = ps[ql][ql + t]
    {
        float* srow = score_out + ((size_t)bh*SEQ + qbase)*BANDW;
        for (int idx = tid; idx < QB*BANDW; idx += 256) {
            int ql = idx / BANDW;
            int t  = idx - ql*BANDW;
            srow[(size_t)ql*BANDW + t] = ps[ql*KB + ql + t];
        }
    }

    // phase 2: out = P @ V  (4 queries x 2 dims per thread)
    float acc[4][2];
#pragma unroll
    for (int i = 0; i < 4; i++) { acc[i][0] = 0.f; acc[i][1] = 0.f; }

    for (int j = 0; j < KB; j += 4) {
        float4 pv[4];
#pragma unroll
        for (int i = 0; i < 4; i++)
            pv[i] = *reinterpret_cast<const float4*>(&ps[(ty*4 + i)*KB + j]);
#pragma unroll
        for (int u = 0; u < 4; u++) {
            float v0 = vv[(j+u)*HDIM + lane];
            float v1 = vv[(j+u)*HDIM + lane + 32];
#pragma unroll
            for (int i = 0; i < 4; i++) {
                float p = (u == 0) ? pv[i].x : (u == 1) ? pv[i].y : (u == 2) ? pv[i].z : pv[i].w;
                acc[i][0] += p*v0;
                acc[i][1] += p*v1;
            }
        }
    }

    const int b = bh >> 3, hh = bh & 7;
#pragma unroll
    for (int i = 0; i < 4; i++) {
        int gi = qbase + ty*4 + i;
        float* dst = g_attn + ((size_t)(b*SEQ + gi))*DMODEL + hh*HDIM;
        dst[lane]      = acc[i][0];
        dst[lane + 32] = acc[i][1];
    }
}

// ---------------- residual + layernorm -----------------------------------------
__global__ __launch_bounds__(128) void ln_kernel(
    const float* __restrict__ a, const float* __restrict__ b,
    const float* __restrict__ gam, const float* __restrict__ bet,
    float* __restrict__ out)
{
    const int row = blockIdx.x;
    const int t = threadIdx.x;
    const float4 x4 = reinterpret_cast<const float4*>(a + (size_t)row*DMODEL)[t];
    const float4 y4 = reinterpret_cast<const float4*>(b + (size_t)row*DMODEL)[t];
    float v0 = x4.x + y4.x, v1 = x4.y + y4.y, v2 = x4.z + y4.z, v3 = x4.w + y4.w;
    float sum = v0+v1+v2+v3;
    float sq  = v0*v0+v1*v1+v2*v2+v3*v3;
#pragma unroll
    for (int off = 16; off > 0; off >>= 1) {
        sum += __shfl_xor_sync(0xffffffffu, sum, off);
        sq  += __shfl_xor_sync(0xffffffffu, sq,  off);
    }
    __shared__ float red[8];
    const int w = t >> 5, l = t & 31;
    if (l == 0) { red[w] = sum; red[4+w] = sq; }
    __syncthreads();
    sum = red[0]+red[1]+red[2]+red[3];
    sq  = red[4]+red[5]+red[6]+red[7];
    const float mu  = sum * (1.f/DMODEL);
    const float var = sq * (1.f/DMODEL) - mu*mu;
    const float rstd = rsqrtf(var + 1e-5f);
    const float4 g4 = reinterpret_cast<const float4*>(gam)[t];
    const float4 b4 = reinterpret_cast<const float4*>(bet)[t];
    float4 o;
    o.x = (v0 - mu)*rstd*g4.x + b4.x;
    o.y = (v1 - mu)*rstd*g4.y + b4.y;
    o.z = (v2 - mu)*rstd*g4.z + b4.z;
    o.w = (v3 - mu)*rstd*g4.w + b4.w;
    reinterpret_cast<float4*>(out + (size_t)row*DMODEL)[t] = o;
}

// ---------------- launch --------------------------------------------------------
extern "C" void kernel_launch(void* const* d_in, const int* in_sizes, int n_in,
                              void* d_out, int out_size)
{
    const float* x    = (const float*)d_in[0];
    const float* Wq   = (const float*)d_in[1];
    const float* bq   = (const float*)d_in[2];
    const float* Wk   = (const float*)d_in[3];
    const float* bk   = (const float*)d_in[4];
    const float* Wv   = (const float*)d_in[5];
    const float* bv   = (const float*)d_in[6];
    const float* ln1g = (const float*)d_in[7];
    const float* ln1b = (const float*)d_in[8];
    const float* Wf1  = (const float*)d_in[9];
    const float* bf1  = (const float*)d_in[10];
    const float* Wf2  = (const float*)d_in[11];
    const float* bf2  = (const float*)d_in[12];
    const float* ln2g = (const float*)d_in[13];
    const float* ln2b = (const float*)d_in[14];

    float* out   = (float*)d_out;
    float* score = out + (size_t)ROWS*DMODEL;   // 8,388,608 offset

    float *q, *k, *v, *attn, *h, *ff1, *ff2;
    cudaGetSymbolAddress((void**)&q,    g_q);
    cudaGetSymbolAddress((void**)&k,    g_k);
    cudaGetSymbolAddress((void**)&v,    g_v);
    cudaGetSymbolAddress((void**)&attn, g_attn);
    cudaGetSymbolAddress((void**)&h,    g_h);
    cudaGetSymbolAddress((void**)&ff1,  g_ff1);
    cudaGetSymbolAddress((void**)&ff2,  g_ff2);

    const int SMEM_ATTN = (64*KB + KB*64 + 64*QB + QB*KB) * (int)sizeof(float); // 192,512
    cudaFuncSetAttribute(attn_kernel, cudaFuncAttributeMaxDynamicSharedMemorySize, SMEM_ATTN);

    // QKV projections (head-major outputs; q pre-scaled by 1/sqrt(64))
    dim3 gq(DMODEL/128, ROWS/128);
    sgemm_kernel<<<gq, 256>>>(x, Wq, bq, q, ROWS, DMODEL, DMODEL, 0, 0.125f);
    sgemm_kernel<<<gq, 256>>>(x, Wk, bk, k, ROWS, DMODEL, DMODEL, 0, 1.0f);
    sgemm_kernel<<<gq, 256>>>(x, Wv, bv, v, ROWS, DMODEL, DMODEL, 0, 1.0f);

    // sliding-window attention (+ band probs straight to output)
    attn_kernel<<<dim3(SEQ/QB, BHS), 256, SMEM_ATTN>>>(score);

    // h = LN(attn + x)
    ln_kernel<<<ROWS, 128>>>(attn, x, ln1g, ln1b, h);

    // FFN
    sgemm_kernel<<<dim3(DHID/128, ROWS/128), 256>>>(h, Wf1, bf1, ff1, ROWS, DHID, DMODEL, 1, 1.0f);
    sgemm_kernel<<<dim3(DMODEL/128, ROWS/128), 256>>>(ff1, Wf2, bf2, ff2, ROWS, DMODEL, DHID, 2, 1.0f);

    // out = LN(ff2 + h)
    ln_kernel<<<ROWS, 128>>>(ff2, h, ln2g, ln2b, out);
}